// round 4
// baseline (speedup 1.0000x reference)
#include <cuda_runtime.h>
#include <math.h>

// ---------------- problem constants ----------------
#define B_ 2
#define N_ 384
#define D_ 256
#define H_ 8
#define DH_ 32
#define PD_ 64
#define L_ 8
#define ROWS_ (B_*N_)      // 768
#define FF_ 1024
#define FEAT_ 320          // D + PD

// ---------------- scratch buffers ----------------
__device__ __align__(16) float g_x   [ROWS_*D_];
__device__ __align__(16) float g_tmp [ROWS_*D_];
__device__ __align__(16) float g_h   [ROWS_*D_];
__device__ __align__(16) float g_qkv [3*ROWS_*D_];
__device__ __align__(16) float g_ao  [ROWS_*D_];
__device__ __align__(16) float g_ffn [ROWS_*FF_];
__device__ __align__(16) float g_proj[ROWS_*PD_];
__device__ __align__(16) float g_pm  [ROWS_*PD_];
__device__ __align__(16) float g_u   [ROWS_*128];
__device__ __align__(16) float g_t   [ROWS_*3];

// ---------------- reductions ----------------
__device__ __forceinline__ float2 block_sum2_256(float a, float b) {
    __shared__ float sa[8], sb[8];
    int lane = threadIdx.x & 31, wid = threadIdx.x >> 5;
#pragma unroll
    for (int o = 16; o > 0; o >>= 1) {
        a += __shfl_xor_sync(0xffffffffu, a, o);
        b += __shfl_xor_sync(0xffffffffu, b, o);
    }
    if (lane == 0) { sa[wid] = a; sb[wid] = b; }
    __syncthreads();
    if (threadIdx.x == 0) {
        float A = sa[0], Bv = sb[0];
        for (int w = 1; w < 8; w++) { A += sa[w]; Bv += sb[w]; }
        sa[0] = A; sb[0] = Bv;
    }
    __syncthreads();
    float2 r = make_float2(sa[0], sb[0]);
    __syncthreads();
    return r;
}

// ---------------- embedding + pos-enc + layernorm ----------------
__global__ void embed_kernel(const int* __restrict__ tokens,
                             const float* __restrict__ tok_emb,
                             const float* __restrict__ w,
                             const float* __restrict__ b,
                             float* __restrict__ out) {
    int row = blockIdx.x;
    int n = row % N_;
    int c = threadIdx.x;
    int tok = tokens[row];
    float val = tok_emb[tok * D_ + c];
    int half = c >> 1;
    float div = expf((float)(2 * half) * (-9.210340371976184f / (float)D_));
    float ang = (float)n * div;
    val += (c & 1) ? cosf(ang) : sinf(ang);
    float2 s = block_sum2_256(val, val * val);
    float m = s.x * (1.f / D_);
    float var = s.y * (1.f / D_) - m * m;
    out[row * D_ + c] = (val - m) * rsqrtf(var + 1e-5f) * w[c] + b[c];
}

// ---------------- dual layernorm: x = LN1(tmp); h = LN2(x) ----------------
__global__ void ln2_kernel(const float* __restrict__ in,
                           const float* __restrict__ w1, const float* __restrict__ b1,
                           const float* __restrict__ w2, const float* __restrict__ b2,
                           float* __restrict__ xo, float* __restrict__ ho) {
    int row = blockIdx.x;
    int c = threadIdx.x;
    float v = in[row * D_ + c];
    float2 s = block_sum2_256(v, v * v);
    float m = s.x * (1.f / D_);
    float var = s.y * (1.f / D_) - m * m;
    float x1 = (v - m) * rsqrtf(var + 1e-5f) * w1[c] + b1[c];
    xo[row * D_ + c] = x1;
    float2 s2 = block_sum2_256(x1, x1 * x1);
    float m2 = s2.x * (1.f / D_);
    float var2 = s2.y * (1.f / D_) - m2 * m2;
    ho[row * D_ + c] = (x1 - m2) * rsqrtf(var2 + 1e-5f) * w2[c] + b2[c];
}

// ---------------- generic double-buffered GEMM ----------------
// MODE 0: plain C = act(A@B0 + bias (+res))
// MODE 1: QKV batched (z picks weight among B0/B1/B2, C offset z*M*N)
// MODE 4: A is concat [x(256) | pm(64)]: A param = x, B1 param = pm
template<int M, int N, int K, int TM, int TN, int ACT, bool RES, int MODE>
__global__ __launch_bounds__(256) void gemm_k(
    const float* __restrict__ A,  const float* __restrict__ B0,
    const float* __restrict__ B1, const float* __restrict__ B2,
    const float* __restrict__ bias, const float* __restrict__ res,
    float* __restrict__ C) {
    constexpr int TX = TN / 4;
    constexpr int TY = 256 / TX;
    constexpr int RM = TM / TY;
    constexpr int S  = K / 16;

    __shared__ alignas(16) float As[2][16][TM];
    __shared__ alignas(16) float Bs[2][16][TN];

    int t = threadIdx.x;
    int m0 = blockIdx.y * TM, n0 = blockIdx.x * TN;
    int z = blockIdx.z;

    const float* Bp = (MODE == 1) ? (z == 0 ? B0 : (z == 1 ? B1 : B2)) : B0;
    float* Cc = (MODE == 1) ? C + (size_t)z * M * N : C;

    int tx = t % TX, ty = t / TX;

    float4 pa = make_float4(0.f, 0.f, 0.f, 0.f), pb = pa;
    auto loadA = [&](int s, float4& r) {
        if (t < TM * 4) {
            int ar = t >> 2, ak = (t & 3) * 4;
            int col = s * 16 + ak;
            if (MODE == 4) {
                const float* src = (col < 256)
                    ? &A[(size_t)(m0 + ar) * 256 + col]
                    : &B1[(size_t)(m0 + ar) * 64 + (col - 256)];
                r = *(const float4*)src;
            } else {
                r = *(const float4*)&A[(size_t)(m0 + ar) * K + col];
            }
        }
    };
    auto storeA = [&](int buf, const float4& r) {
        if (t < TM * 4) {
            int ar = t >> 2, ak = (t & 3) * 4;
            As[buf][ak + 0][ar] = r.x; As[buf][ak + 1][ar] = r.y;
            As[buf][ak + 2][ar] = r.z; As[buf][ak + 3][ar] = r.w;
        }
    };
    auto loadB = [&](int s, float4& r) {
        if (t < TN * 4) {
            int br = t / TX, bc = (t % TX) * 4;
            r = *(const float4*)&Bp[(size_t)(s * 16 + br) * N + n0 + bc];
        }
    };
    auto storeB = [&](int buf, const float4& r) {
        if (t < TN * 4) {
            int br = t / TX, bc = (t % TX) * 4;
            *(float4*)&Bs[buf][br][bc] = r;
        }
    };

    loadA(0, pa); loadB(0, pb);
    storeA(0, pa); storeB(0, pb);
    __syncthreads();

    float acc[RM][4];
#pragma unroll
    for (int i = 0; i < RM; i++)
#pragma unroll
        for (int j = 0; j < 4; j++) acc[i][j] = 0.f;

#pragma unroll 2
    for (int s = 0; s < S; s++) {
        int buf = s & 1;
        if (s + 1 < S) { loadA(s + 1, pa); loadB(s + 1, pb); }
#pragma unroll
        for (int k = 0; k < 16; k++) {
            float rb[4];
#pragma unroll
            for (int j = 0; j < 4; j++) rb[j] = Bs[buf][k][tx * 4 + j];
#pragma unroll
            for (int i = 0; i < RM; i++) {
                float ra = As[buf][k][ty * RM + i];
#pragma unroll
                for (int j = 0; j < 4; j++) acc[i][j] = fmaf(ra, rb[j], acc[i][j]);
            }
        }
        if (s + 1 < S) { storeA((s + 1) & 1, pa); storeB((s + 1) & 1, pb); }
        __syncthreads();
    }

#pragma unroll
    for (int i = 0; i < RM; i++) {
        int m = m0 + ty * RM + i;
#pragma unroll
        for (int j = 0; j < 4; j++) {
            int n = n0 + tx * 4 + j;
            float v = acc[i][j];
            if (bias) v += bias[n];
            if (RES) v += res[(size_t)m * N + n];
            if (ACT == 1) v = fmaxf(v, 0.f);
            else if (ACT == 2) v = 0.5f * v * (1.f + erff(v * 0.7071067811865475f));
            else if (ACT == 3) v = v / (1.f + __expf(-v));
            Cc[(size_t)m * N + n] = v;
        }
    }
}

// ---------------- fused flash attention with SE3 distance bias ----------------
// grid (12, 16): x = 32-row i-tile, y = z = b*8+h. 256 threads.
__global__ __launch_bounds__(256) void attn_fused(
        const float* __restrict__ Q, const float* __restrict__ Km,
        const float* __restrict__ V, const float* __restrict__ tb,
        float* __restrict__ ao) {
    __shared__ alignas(16) float qs[32][36];
    __shared__ alignas(16) float ks[64][36];
    __shared__ alignas(16) float vs[64][32];
    __shared__ alignas(16) float ps[32][64];
    __shared__ float tjs[64 * 3];
    __shared__ float tis[32 * 3];
    __shared__ float scl[32];
    __shared__ float invs[32];

    int t = threadIdx.x;
    int i0 = blockIdx.x * 32;
    int z = blockIdx.y;
    int b = z >> 3, h = z & 7;
    const float* Qb = Q  + ((size_t)(b * N_) + i0) * D_ + h * DH_;
    const float* Kb = Km + (size_t)(b * N_) * D_ + h * DH_;
    const float* Vb = V  + (size_t)(b * N_) * D_ + h * DH_;

    {   // load Q tile (32x32)
        int r = t >> 3, k4 = (t & 7) * 4;
        *(float4*)&qs[r][k4] = *(const float4*)&Qb[(size_t)r * D_ + k4];
    }
    if (t < 96) tis[t] = tb[(size_t)(b * N_ + i0) * 3 + t];

    int w = t >> 5, l = t & 31;
    float m_run[4] = {-1e30f, -1e30f, -1e30f, -1e30f};
    float s_run[4] = {0.f, 0.f, 0.f, 0.f};
    float4 oacc = make_float4(0.f, 0.f, 0.f, 0.f);
    int iI = t >> 3, d4 = (t & 7) << 2;

    const float SCALE = 0.17677669529663687f;   // 1/sqrt(32)

    for (int c = 0; c < 6; c++) {
        int j0 = c * 64;
#pragma unroll
        for (int it = 0; it < 2; it++) {
            int f = t + it * 256;
            int j = f >> 3, k4 = (f & 7) * 4;
            *(float4*)&ks[j][k4] = *(const float4*)&Kb[(size_t)(j0 + j) * D_ + k4];
            *(float4*)&vs[j][k4] = *(const float4*)&Vb[(size_t)(j0 + j) * D_ + k4];
        }
        if (t < 192) tjs[t] = tb[(size_t)(b * N_ + j0) * 3 + t];
        __syncthreads();

        // scores for 64-col chunk: warp w owns rows w*4..w*4+3; lane l cols l, l+32
        float acc[4][2];
#pragma unroll
        for (int rr = 0; rr < 4; rr++) { acc[rr][0] = 0.f; acc[rr][1] = 0.f; }
#pragma unroll
        for (int k4 = 0; k4 < 8; k4++) {
            float4 k0 = *(float4*)&ks[l][k4 * 4];
            float4 k1 = *(float4*)&ks[l + 32][k4 * 4];
#pragma unroll
            for (int rr = 0; rr < 4; rr++) {
                float4 qv = *(float4*)&qs[w * 4 + rr][k4 * 4];
                acc[rr][0] += qv.x * k0.x + qv.y * k0.y + qv.z * k0.z + qv.w * k0.w;
                acc[rr][1] += qv.x * k1.x + qv.y * k1.y + qv.z * k1.z + qv.w * k1.w;
            }
        }
        float tjx0 = tjs[l * 3], tjy0 = tjs[l * 3 + 1], tjz0 = tjs[l * 3 + 2];
        float tjx1 = tjs[(l + 32) * 3], tjy1 = tjs[(l + 32) * 3 + 1], tjz1 = tjs[(l + 32) * 3 + 2];
#pragma unroll
        for (int rr = 0; rr < 4; rr++) {
            int r = w * 4 + rr;
            float tx = tis[r * 3], ty = tis[r * 3 + 1], tz = tis[r * 3 + 2];
            float dx = tx - tjx0, dy = ty - tjy0, dz = tz - tjz0;
            float s0 = acc[rr][0] * SCALE - (dx * dx + dy * dy + dz * dz);
            dx = tx - tjx1; dy = ty - tjy1; dz = tz - tjz1;
            float s1 = acc[rr][1] * SCALE - (dx * dx + dy * dy + dz * dz);
            float cm = fmaxf(s0, s1);
#pragma unroll
            for (int o = 16; o > 0; o >>= 1) cm = fmaxf(cm, __shfl_xor_sync(0xffffffffu, cm, o));
            float mn = fmaxf(m_run[rr], cm);
            float corr = __expf(m_run[rr] - mn);
            float p0 = __expf(s0 - mn), p1 = __expf(s1 - mn);
            float cs = p0 + p1;
#pragma unroll
            for (int o = 16; o > 0; o >>= 1) cs += __shfl_xor_sync(0xffffffffu, cs, o);
            s_run[rr] = s_run[rr] * corr + cs;
            m_run[rr] = mn;
            ps[r][l] = p0; ps[r][l + 32] = p1;
            if (l == 0) scl[r] = corr;
        }
        __syncthreads();

        // AV accumulate: thread (iI, d4)
        {
            float sc_ = scl[iI];
            oacc.x *= sc_; oacc.y *= sc_; oacc.z *= sc_; oacc.w *= sc_;
#pragma unroll
            for (int j = 0; j < 64; j += 4) {
                float4 p4 = *(float4*)&ps[iI][j];
                float4 v0 = *(float4*)&vs[j + 0][d4];
                float4 v1 = *(float4*)&vs[j + 1][d4];
                float4 v2 = *(float4*)&vs[j + 2][d4];
                float4 v3 = *(float4*)&vs[j + 3][d4];
                oacc.x += p4.x * v0.x + p4.y * v1.x + p4.z * v2.x + p4.w * v3.x;
                oacc.y += p4.x * v0.y + p4.y * v1.y + p4.z * v2.y + p4.w * v3.y;
                oacc.z += p4.x * v0.z + p4.y * v1.z + p4.z * v2.z + p4.w * v3.z;
                oacc.w += p4.x * v0.w + p4.y * v1.w + p4.z * v2.w + p4.w * v3.w;
            }
        }
        __syncthreads();
    }

    if (l == 0) {
#pragma unroll
        for (int rr = 0; rr < 4; rr++) invs[w * 4 + rr] = 1.f / s_run[rr];
    }
    __syncthreads();
    float iv = invs[iI];
    float* dst = ao + ((size_t)(b * N_ + i0 + iI)) * D_ + h * DH_ + d4;
    *(float4*)dst = make_float4(oacc.x * iv, oacc.y * iv, oacc.z * iv, oacc.w * iv);
}

// ---------------- fused pair LN + mean: warp-per-j, 512 threads ----------------
__global__ __launch_bounds__(512) void pair_kernel(
        const float* __restrict__ proj, const float* __restrict__ relpos,
        const float* __restrict__ pw, const float* __restrict__ pb,
        float* __restrict__ pm) {
    int row = blockIdx.x;
    int b = row / N_, i = row % N_;
    int t = threadIdx.x;
    int w = t >> 5, l = t & 31;

    __shared__ float pi[PD_];
    __shared__ float accs[16][PD_];

    if (t < PD_) pi[t] = proj[row * PD_ + t];
    __syncthreads();

    float w0 = pw[l], w1 = pw[l + 32], bb0 = pb[l], bb1 = pb[l + 32];
    float p0 = pi[l], p1 = pi[l + 32];
    float a0 = 0.f, a1 = 0.f;
    for (int j = w; j < N_; j += 16) {
        int rel = min(64, max(-64, j - i)) + 64;
        const float* pj = proj + (size_t)(b * N_ + j) * PD_;
        const float* re = relpos + (size_t)rel * PD_;
        float v0 = p0 + pj[l] + re[l];
        float v1 = p1 + pj[l + 32] + re[l + 32];
        float s = v0 + v1, s2 = v0 * v0 + v1 * v1;
#pragma unroll
        for (int o = 16; o > 0; o >>= 1) {
            s  += __shfl_xor_sync(0xffffffffu, s, o);
            s2 += __shfl_xor_sync(0xffffffffu, s2, o);
        }
        float m = s * (1.f / PD_);
        float var = s2 * (1.f / PD_) - m * m;
        float rs = rsqrtf(var + 1e-5f);
        a0 += (v0 - m) * rs * w0 + bb0;
        a1 += (v1 - m) * rs * w1 + bb1;
    }
    accs[w][l] = a0; accs[w][l + 32] = a1;
    __syncthreads();
    if (t < PD_) {
        float s = 0.f;
#pragma unroll
        for (int ww = 0; ww < 16; ww++) s += accs[ww][t];
        pm[row * PD_ + t] = s * (1.f / N_);
    }
}

// ---------------- raw = u@Wf2 + bf2; rot6d; frames + t ----------------
__global__ void frame_kernel(const float* __restrict__ u, const float* __restrict__ Wf2,
                             const float* __restrict__ bf2,
                             float* __restrict__ frames, float* __restrict__ tb) {
    int row = blockIdx.x;
    int t = threadIdx.x;
    __shared__ float us[128];
    __shared__ float raw[9];
    us[t] = u[row * 128 + t];
    __syncthreads();
    if (t < 9) {
        float s = bf2[t];
        for (int k = 0; k < 128; k++) s += us[k] * Wf2[k * 9 + t];
        raw[t] = s;
    }
    __syncthreads();
    if (t == 0) {
        float a1x = raw[0], a1y = raw[1], a1z = raw[2];
        float a2x = raw[3], a2y = raw[4], a2z = raw[5];
        float n1 = sqrtf(a1x * a1x + a1y * a1y + a1z * a1z + 1e-8f);
        float b1x = a1x / n1, b1y = a1y / n1, b1z = a1z / n1;
        float d = b1x * a2x + b1y * a2y + b1z * a2z;
        float px = a2x - d * b1x, py = a2y - d * b1y, pz = a2z - d * b1z;
        float n2 = sqrtf(px * px + py * py + pz * pz + 1e-8f);
        float b2x = px / n2, b2y = py / n2, b2z = pz / n2;
        float b3x = b1y * b2z - b1z * b2y;
        float b3y = b1z * b2x - b1x * b2z;
        float b3z = b1x * b2y - b1y * b2x;
        float tx = raw[6], ty = raw[7], tz = raw[8];
        float* F = frames + (size_t)row * 16;
        F[0] = b1x; F[1] = b1y; F[2]  = b1z; F[3]  = tx;
        F[4] = b2x; F[5] = b2y; F[6]  = b2z; F[7]  = ty;
        F[8] = b3x; F[9] = b3y; F[10] = b3z; F[11] = tz;
        F[12] = 0.f; F[13] = 0.f; F[14] = 0.f; F[15] = 1.f;
        tb[row * 3 + 0] = tx; tb[row * 3 + 1] = ty; tb[row * 3 + 2] = tz;
    }
}

// ---------------- utility ----------------
__global__ void zero_kernel(float* p, int n) {
    int i = blockIdx.x * blockDim.x + threadIdx.x;
    if (i < n) p[i] = 0.f;
}
__global__ void copy_kernel(const float* __restrict__ src, float* __restrict__ dst) {
    dst[blockIdx.x * blockDim.x + threadIdx.x] = src[blockIdx.x * blockDim.x + threadIdx.x];
}

// ---------------- host ----------------
extern "C" void kernel_launch(void* const* d_in, const int* in_sizes, int n_in,
                              void* d_out, int out_size) {
    (void)in_sizes; (void)n_in; (void)out_size;
    const int*   tokens     = (const int*)d_in[0];
    const float* tok_emb    = (const float*)d_in[1];
    const float* emb_ln_w   = (const float*)d_in[2];
    const float* emb_ln_b   = (const float*)d_in[3];
    const float* Wq         = (const float*)d_in[4];
    const float* Wk         = (const float*)d_in[5];
    const float* Wv         = (const float*)d_in[6];
    const float* Wo         = (const float*)d_in[7];
    const float* bo         = (const float*)d_in[8];
    const float* attn_ln_w  = (const float*)d_in[9];
    const float* attn_ln_b  = (const float*)d_in[10];
    const float* ff_ln_w    = (const float*)d_in[11];
    const float* ff_ln_b    = (const float*)d_in[12];
    const float* W1         = (const float*)d_in[13];
    const float* b1         = (const float*)d_in[14];
    const float* W2         = (const float*)d_in[15];
    const float* b2         = (const float*)d_in[16];
    const float* Wop        = (const float*)d_in[17];
    const float* bop        = (const float*)d_in[18];
    const float* relpos     = (const float*)d_in[19];
    const float* pair_ln_w  = (const float*)d_in[20];
    const float* pair_ln_b  = (const float*)d_in[21];
    const float* Wf1        = (const float*)d_in[22];
    const float* bf1        = (const float*)d_in[23];
    const float* Wf2        = (const float*)d_in[24];
    const float* bf2        = (const float*)d_in[25];

    float *x, *tmp, *h, *qkv, *ao, *ffn, *proj, *pm, *u, *tb;
    cudaGetSymbolAddress((void**)&x,   g_x);
    cudaGetSymbolAddress((void**)&tmp, g_tmp);
    cudaGetSymbolAddress((void**)&h,   g_h);
    cudaGetSymbolAddress((void**)&qkv, g_qkv);
    cudaGetSymbolAddress((void**)&ao,  g_ao);
    cudaGetSymbolAddress((void**)&ffn, g_ffn);
    cudaGetSymbolAddress((void**)&proj,g_proj);
    cudaGetSymbolAddress((void**)&pm,  g_pm);
    cudaGetSymbolAddress((void**)&u,   g_u);
    cudaGetSymbolAddress((void**)&tb,  g_t);

    float* q = qkv;
    float* k = qkv + (size_t)ROWS_ * D_;
    float* v = qkv + (size_t)2 * ROWS_ * D_;

    float* fout = (float*)d_out;                 // frames: ROWS_*16
    float* xout = fout + ROWS_ * 16;             // x: ROWS_*D_

    zero_kernel<<<(ROWS_ * 3 + 255) / 256, 256>>>(tb, ROWS_ * 3);
    embed_kernel<<<ROWS_, 256>>>(tokens, tok_emb, emb_ln_w, emb_ln_b, x);

    for (int l = 0; l < L_; l++) {
        const float* Wql = Wq + (size_t)l * D_ * D_;
        const float* Wkl = Wk + (size_t)l * D_ * D_;
        const float* Wvl = Wv + (size_t)l * D_ * D_;
        const float* Wol = Wo + (size_t)l * D_ * D_;
        const float* bol = bo + (size_t)l * D_;
        const float* W1l = W1 + (size_t)l * D_ * FF_;
        const float* b1l = b1 + (size_t)l * FF_;
        const float* W2l = W2 + (size_t)l * FF_ * D_;
        const float* b2l = b2 + (size_t)l * D_;

        // fused QKV
        gemm_k<ROWS_, D_, D_, 64, 64, 0, false, 1>
            <<<dim3(4, 12, 3), 256>>>(x, Wql, Wkl, Wvl, nullptr, nullptr, qkv);

        // fused flash attention (scores + d2 bias + softmax + AV)
        attn_fused<<<dim3(12, 16), 256>>>(q, k, v, tb, ao);

        // tmp = x + ao@Wo + bo
        gemm_k<ROWS_, D_, D_, 32, 64, 0, true, 0>
            <<<dim3(4, 24), 256>>>(ao, Wol, nullptr, nullptr, bol, x, tmp);
        // x = LN1(tmp); h = LN2(x)
        ln2_kernel<<<ROWS_, 256>>>(tmp, attn_ln_w + l * D_, attn_ln_b + l * D_,
                                   ff_ln_w + l * D_, ff_ln_b + l * D_, x, h);

        // FFN
        gemm_k<ROWS_, FF_, D_, 64, 64, 2, false, 0>
            <<<dim3(16, 12), 256>>>(h, W1l, nullptr, nullptr, b1l, nullptr, ffn);
        gemm_k<ROWS_, D_, FF_, 32, 64, 0, true, 0>
            <<<dim3(4, 24), 256>>>(ffn, W2l, nullptr, nullptr, b2l, x, x);

        // proj = relu(x@Wop + bop)
        gemm_k<ROWS_, PD_, D_, 32, 64, 1, false, 0>
            <<<dim3(1, 24), 256>>>(x, Wop, nullptr, nullptr, bop, nullptr, proj);

        // pair LN + mean (fused)
        pair_kernel<<<ROWS_, 512>>>(proj, relpos, pair_ln_w, pair_ln_b, pm);

        // u = silu([x|pm]@Wf1 + bf1)  (concat fused into A-load)
        gemm_k<ROWS_, 128, FEAT_, 32, 64, 3, false, 4>
            <<<dim3(2, 24), 256>>>(x, Wf1, pm, nullptr, bf1, nullptr, u);

        // frames (into d_out) + t buffer
        frame_kernel<<<ROWS_, 128>>>(u, Wf2, bf2, fout, tb);
    }

    copy_kernel<<<ROWS_, 256>>>(x, xout);
}

// round 5
// speedup vs baseline: 1.0011x; 1.0011x over previous
#include <cuda_runtime.h>
#include <math.h>

// ---------------- problem constants ----------------
#define B_ 2
#define N_ 384
#define D_ 256
#define H_ 8
#define DH_ 32
#define PD_ 64
#define L_ 8
#define ROWS_ (B_*N_)      // 768
#define FF_ 1024
#define FEAT_ 320          // D + PD

// ---------------- scratch buffers ----------------
__device__ __align__(16) float g_x   [ROWS_*D_];
__device__ __align__(16) float g_tmp [ROWS_*D_];
__device__ __align__(16) float g_h   [ROWS_*D_];
__device__ __align__(16) float g_qkv [3*ROWS_*D_];
__device__ __align__(16) float g_ao  [ROWS_*D_];
__device__ __align__(16) float g_ffn [ROWS_*FF_];
__device__ __align__(16) float g_s   [16*384*384];   // scores [b*8+h][i][j]
__device__ __align__(16) float g_proj[ROWS_*PD_];
__device__ __align__(16) float g_pm  [ROWS_*PD_];
__device__ __align__(16) float g_u   [ROWS_*128];
__device__ __align__(16) float g_t   [ROWS_*3];

// ---------------- reductions ----------------
__device__ __forceinline__ float2 block_sum2_256(float a, float b) {
    __shared__ float sa[8], sb[8];
    int lane = threadIdx.x & 31, wid = threadIdx.x >> 5;
#pragma unroll
    for (int o = 16; o > 0; o >>= 1) {
        a += __shfl_xor_sync(0xffffffffu, a, o);
        b += __shfl_xor_sync(0xffffffffu, b, o);
    }
    if (lane == 0) { sa[wid] = a; sb[wid] = b; }
    __syncthreads();
    if (threadIdx.x == 0) {
        float A = sa[0], Bv = sb[0];
        for (int w = 1; w < 8; w++) { A += sa[w]; Bv += sb[w]; }
        sa[0] = A; sb[0] = Bv;
    }
    __syncthreads();
    float2 r = make_float2(sa[0], sb[0]);
    __syncthreads();
    return r;
}

// ---------------- embedding + pos-enc + layernorm ----------------
__global__ void embed_kernel(const int* __restrict__ tokens,
                             const float* __restrict__ tok_emb,
                             const float* __restrict__ w,
                             const float* __restrict__ b,
                             float* __restrict__ out) {
    int row = blockIdx.x;
    int n = row % N_;
    int c = threadIdx.x;
    int tok = tokens[row];
    float val = tok_emb[tok * D_ + c];
    int half = c >> 1;
    float div = expf((float)(2 * half) * (-9.210340371976184f / (float)D_));
    float ang = (float)n * div;
    val += (c & 1) ? cosf(ang) : sinf(ang);
    float2 s = block_sum2_256(val, val * val);
    float m = s.x * (1.f / D_);
    float var = s.y * (1.f / D_) - m * m;
    out[row * D_ + c] = (val - m) * rsqrtf(var + 1e-5f) * w[c] + b[c];
}

// ---------------- dual layernorm: x = LN1(tmp); h = LN2(x) ----------------
__global__ void ln2_kernel(const float* __restrict__ in,
                           const float* __restrict__ w1, const float* __restrict__ b1,
                           const float* __restrict__ w2, const float* __restrict__ b2,
                           float* __restrict__ xo, float* __restrict__ ho) {
    int row = blockIdx.x;
    int c = threadIdx.x;
    float v = in[row * D_ + c];
    float2 s = block_sum2_256(v, v * v);
    float m = s.x * (1.f / D_);
    float var = s.y * (1.f / D_) - m * m;
    float x1 = (v - m) * rsqrtf(var + 1e-5f) * w1[c] + b1[c];
    xo[row * D_ + c] = x1;
    float2 s2 = block_sum2_256(x1, x1 * x1);
    float m2 = s2.x * (1.f / D_);
    float var2 = s2.y * (1.f / D_) - m2 * m2;
    ho[row * D_ + c] = (x1 - m2) * rsqrtf(var2 + 1e-5f) * w2[c] + b2[c];
}

// ---------------- generic double-buffered GEMM ----------------
// MODE 0: plain C = act(A@B0 + bias (+res))
// MODE 1: QKV batched (z picks weight among B0/B1/B2, C offset z*M*N)
// MODE 2: scores, batched over z=(b*8+h): A=Q(b,:,h), B=K(b,:,h) transposed,
//         C[z] = (A@B^T)/sqrt(32) - d2(i,j)   (tb = translations)
// MODE 3: AV batched: A=P[z], B=V(b,:,h), C=ao(b,:,h)
// MODE 4: A is concat [x(256) | pm(64)]: A param = x, B1 param = pm
template<int M, int N, int K, int TM, int TN, int ACT, bool RES, int MODE>
__global__ __launch_bounds__(256) void gemm_k(
    const float* __restrict__ Abase, const float* __restrict__ Bb0,
    const float* __restrict__ Bb1,   const float* __restrict__ Bb2,
    const float* __restrict__ bias,  const float* __restrict__ res,
    float* __restrict__ Cbase,       const float* __restrict__ tb) {
    constexpr int TX = TN / 4;
    constexpr int TY = 256 / TX;
    constexpr int RM = TM / TY;
    constexpr int S  = K / 16;

    __shared__ alignas(16) float As[2][16][TM];
    __shared__ alignas(16) float Bs[2][16][TN];

    int t = threadIdx.x;
    int m0 = blockIdx.y * TM, n0 = blockIdx.x * TN;
    int z = blockIdx.z;

    const float* A; const float* Bp; float* C;
    int lda, ldb, ldc;
    int bidx = 0;
    if (MODE == 0 || MODE == 4) { A = Abase; Bp = Bb0; C = Cbase; lda = K; ldb = N; ldc = N; }
    else if (MODE == 1) {
        A = Abase; Bp = (z == 0) ? Bb0 : (z == 1) ? Bb1 : Bb2;
        C = Cbase + (size_t)z * M * N; lda = K; ldb = N; ldc = N;
    } else if (MODE == 2) {
        bidx = z >> 3; int h = z & 7;
        A  = Abase + (size_t)bidx * N_ * D_ + h * DH_;
        Bp = Bb0   + (size_t)bidx * N_ * D_ + h * DH_;
        C  = Cbase + (size_t)z * M * N;
        lda = D_; ldb = D_; ldc = N;
    } else {
        bidx = z >> 3; int h = z & 7;
        A  = Abase + (size_t)z * M * K;
        Bp = Bb0   + (size_t)bidx * N_ * D_ + h * DH_;
        C  = Cbase + (size_t)bidx * N_ * D_ + h * DH_;
        lda = K; ldb = D_; ldc = D_;
    }

    int tx = t % TX, ty = t / TX;

    float4 pa = make_float4(0.f, 0.f, 0.f, 0.f), pb = pa;
    auto loadA = [&](int s, float4& r) {
        if (t < TM * 4) {
            int ar = t >> 2, ak = (t & 3) * 4;
            int col = s * 16 + ak;
            if (MODE == 4) {
                const float* src = (col < 256)
                    ? &Abase[(size_t)(m0 + ar) * 256 + col]
                    : &Bb1[(size_t)(m0 + ar) * 64 + (col - 256)];
                r = *(const float4*)src;
            } else {
                r = *(const float4*)&A[(size_t)(m0 + ar) * lda + col];
            }
        }
    };
    auto storeA = [&](int buf, const float4& r) {
        if (t < TM * 4) {
            int ar = t >> 2, ak = (t & 3) * 4;
            As[buf][ak + 0][ar] = r.x; As[buf][ak + 1][ar] = r.y;
            As[buf][ak + 2][ar] = r.z; As[buf][ak + 3][ar] = r.w;
        }
    };
    auto loadB = [&](int s, float4& r) {
        if (MODE == 2) {
            if (t < TN * 4) {
                int br = t >> 2, bk = (t & 3) * 4;
                r = *(const float4*)&Bp[(size_t)(n0 + br) * ldb + s * 16 + bk];
            }
        } else {
            if (t < TN * 4) {
                int br = t / TX, bc = (t % TX) * 4;
                r = *(const float4*)&Bp[(size_t)(s * 16 + br) * ldb + n0 + bc];
            }
        }
    };
    auto storeB = [&](int buf, const float4& r) {
        if (MODE == 2) {
            if (t < TN * 4) {
                int br = t >> 2, bk = (t & 3) * 4;
                Bs[buf][bk + 0][br] = r.x; Bs[buf][bk + 1][br] = r.y;
                Bs[buf][bk + 2][br] = r.z; Bs[buf][bk + 3][br] = r.w;
            }
        } else {
            if (t < TN * 4) {
                int br = t / TX, bc = (t % TX) * 4;
                *(float4*)&Bs[buf][br][bc] = r;
            }
        }
    };

    loadA(0, pa); loadB(0, pb);
    storeA(0, pa); storeB(0, pb);
    __syncthreads();

    float acc[RM][4];
#pragma unroll
    for (int i = 0; i < RM; i++)
#pragma unroll
        for (int j = 0; j < 4; j++) acc[i][j] = 0.f;

#pragma unroll 2
    for (int s = 0; s < S; s++) {
        int buf = s & 1;
        if (s + 1 < S) { loadA(s + 1, pa); loadB(s + 1, pb); }
#pragma unroll
        for (int k = 0; k < 16; k++) {
            float rb[4];
#pragma unroll
            for (int j = 0; j < 4; j++) rb[j] = Bs[buf][k][tx * 4 + j];
#pragma unroll
            for (int i = 0; i < RM; i++) {
                float ra = As[buf][k][ty * RM + i];
#pragma unroll
                for (int j = 0; j < 4; j++) acc[i][j] = fmaf(ra, rb[j], acc[i][j]);
            }
        }
        if (s + 1 < S) { storeA((s + 1) & 1, pa); storeB((s + 1) & 1, pb); }
        __syncthreads();
    }

    // epilogue
    float tix[RM], tiy[RM], tiz[RM], tjx[4], tjy[4], tjz[4];
    if (MODE == 2) {
        const float* tbb = tb + (size_t)bidx * N_ * 3;
#pragma unroll
        for (int i = 0; i < RM; i++) {
            int m = m0 + ty * RM + i;
            tix[i] = tbb[m * 3 + 0]; tiy[i] = tbb[m * 3 + 1]; tiz[i] = tbb[m * 3 + 2];
        }
#pragma unroll
        for (int j = 0; j < 4; j++) {
            int n = n0 + tx * 4 + j;
            tjx[j] = tbb[n * 3 + 0]; tjy[j] = tbb[n * 3 + 1]; tjz[j] = tbb[n * 3 + 2];
        }
    }
#pragma unroll
    for (int i = 0; i < RM; i++) {
        int m = m0 + ty * RM + i;
#pragma unroll
        for (int j = 0; j < 4; j++) {
            int n = n0 + tx * 4 + j;
            float v = acc[i][j];
            if (MODE == 2) {
                float dx = tix[i] - tjx[j], dy = tiy[i] - tjy[j], dz = tiz[i] - tjz[j];
                v = v * 0.17677669529663687f - (dx * dx + dy * dy + dz * dz);
            }
            if (bias) v += bias[n];
            if (RES) v += res[(size_t)m * ldc + n];
            if (ACT == 1) v = fmaxf(v, 0.f);
            else if (ACT == 2) v = 0.5f * v * (1.f + erff(v * 0.7071067811865475f));
            else if (ACT == 3) v = v / (1.f + __expf(-v));
            C[(size_t)m * ldc + n] = v;
        }
    }
}

// ---------------- warp-per-row softmax over rows of length 384 ----------------
__global__ void softmax_kernel(float* __restrict__ S) {
    int r = blockIdx.x * 8 + (threadIdx.x >> 5);
    int l = threadIdx.x & 31;
    float* row = S + (size_t)r * 384;
    float v[12];
    float mx = -1e30f;
#pragma unroll
    for (int q = 0; q < 12; q++) { v[q] = row[l + q * 32]; mx = fmaxf(mx, v[q]); }
#pragma unroll
    for (int o = 16; o > 0; o >>= 1) mx = fmaxf(mx, __shfl_xor_sync(0xffffffffu, mx, o));
    float s = 0.f;
#pragma unroll
    for (int q = 0; q < 12; q++) { v[q] = __expf(v[q] - mx); s += v[q]; }
#pragma unroll
    for (int o = 16; o > 0; o >>= 1) s += __shfl_xor_sync(0xffffffffu, s, o);
    float inv = 1.f / s;
#pragma unroll
    for (int q = 0; q < 12; q++) row[l + q * 32] = v[q] * inv;
}

// ---------------- fused pair LN + mean: warp-per-j, 512 threads ----------------
__global__ __launch_bounds__(512) void pair_kernel(
        const float* __restrict__ proj, const float* __restrict__ relpos,
        const float* __restrict__ pw, const float* __restrict__ pb,
        float* __restrict__ pm) {
    int row = blockIdx.x;
    int b = row / N_, i = row % N_;
    int t = threadIdx.x;
    int w = t >> 5, l = t & 31;

    __shared__ float pi[PD_];
    __shared__ float accs[16][PD_];

    if (t < PD_) pi[t] = proj[row * PD_ + t];
    __syncthreads();

    float w0 = pw[l], w1 = pw[l + 32], bb0 = pb[l], bb1 = pb[l + 32];
    float p0 = pi[l], p1 = pi[l + 32];
    float a0 = 0.f, a1 = 0.f;
    for (int j = w; j < N_; j += 16) {
        int rel = min(64, max(-64, j - i)) + 64;
        const float* pj = proj + (size_t)(b * N_ + j) * PD_;
        const float* re = relpos + (size_t)rel * PD_;
        float v0 = p0 + pj[l] + re[l];
        float v1 = p1 + pj[l + 32] + re[l + 32];
        float s = v0 + v1, s2 = v0 * v0 + v1 * v1;
#pragma unroll
        for (int o = 16; o > 0; o >>= 1) {
            s  += __shfl_xor_sync(0xffffffffu, s, o);
            s2 += __shfl_xor_sync(0xffffffffu, s2, o);
        }
        float m = s * (1.f / PD_);
        float var = s2 * (1.f / PD_) - m * m;
        float rs = rsqrtf(var + 1e-5f);
        a0 += (v0 - m) * rs * w0 + bb0;
        a1 += (v1 - m) * rs * w1 + bb1;
    }
    accs[w][l] = a0; accs[w][l + 32] = a1;
    __syncthreads();
    if (t < PD_) {
        float s = 0.f;
#pragma unroll
        for (int ww = 0; ww < 16; ww++) s += accs[ww][t];
        pm[row * PD_ + t] = s * (1.f / N_);
    }
}

// ---------------- raw = u@Wf2 + bf2; rot6d; frames + t ----------------
__global__ void frame_kernel(const float* __restrict__ u, const float* __restrict__ Wf2,
                             const float* __restrict__ bf2,
                             float* __restrict__ frames, float* __restrict__ tb) {
    int row = blockIdx.x;
    int t = threadIdx.x;
    __shared__ float us[128];
    __shared__ float raw[9];
    us[t] = u[row * 128 + t];
    __syncthreads();
    if (t < 9) {
        float s = bf2[t];
        for (int k = 0; k < 128; k++) s += us[k] * Wf2[k * 9 + t];
        raw[t] = s;
    }
    __syncthreads();
    if (t == 0) {
        float a1x = raw[0], a1y = raw[1], a1z = raw[2];
        float a2x = raw[3], a2y = raw[4], a2z = raw[5];
        float n1 = sqrtf(a1x * a1x + a1y * a1y + a1z * a1z + 1e-8f);
        float b1x = a1x / n1, b1y = a1y / n1, b1z = a1z / n1;
        float d = b1x * a2x + b1y * a2y + b1z * a2z;
        float px = a2x - d * b1x, py = a2y - d * b1y, pz = a2z - d * b1z;
        float n2 = sqrtf(px * px + py * py + pz * pz + 1e-8f);
        float b2x = px / n2, b2y = py / n2, b2z = pz / n2;
        float b3x = b1y * b2z - b1z * b2y;
        float b3y = b1z * b2x - b1x * b2z;
        float b3z = b1x * b2y - b1y * b2x;
        float tx = raw[6], ty = raw[7], tz = raw[8];
        float* F = frames + (size_t)row * 16;
        F[0] = b1x; F[1] = b1y; F[2]  = b1z; F[3]  = tx;
        F[4] = b2x; F[5] = b2y; F[6]  = b2z; F[7]  = ty;
        F[8] = b3x; F[9] = b3y; F[10] = b3z; F[11] = tz;
        F[12] = 0.f; F[13] = 0.f; F[14] = 0.f; F[15] = 1.f;
        tb[row * 3 + 0] = tx; tb[row * 3 + 1] = ty; tb[row * 3 + 2] = tz;
    }
}

// ---------------- utility ----------------
__global__ void zero_kernel(float* p, int n) {
    int i = blockIdx.x * blockDim.x + threadIdx.x;
    if (i < n) p[i] = 0.f;
}
__global__ void copy_kernel(const float* __restrict__ src, float* __restrict__ dst) {
    dst[blockIdx.x * blockDim.x + threadIdx.x] = src[blockIdx.x * blockDim.x + threadIdx.x];
}

// ---------------- host ----------------
extern "C" void kernel_launch(void* const* d_in, const int* in_sizes, int n_in,
                              void* d_out, int out_size) {
    (void)in_sizes; (void)n_in; (void)out_size;
    const int*   tokens     = (const int*)d_in[0];
    const float* tok_emb    = (const float*)d_in[1];
    const float* emb_ln_w   = (const float*)d_in[2];
    const float* emb_ln_b   = (const float*)d_in[3];
    const float* Wq         = (const float*)d_in[4];
    const float* Wk         = (const float*)d_in[5];
    const float* Wv         = (const float*)d_in[6];
    const float* Wo         = (const float*)d_in[7];
    const float* bo         = (const float*)d_in[8];
    const float* attn_ln_w  = (const float*)d_in[9];
    const float* attn_ln_b  = (const float*)d_in[10];
    const float* ff_ln_w    = (const float*)d_in[11];
    const float* ff_ln_b    = (const float*)d_in[12];
    const float* W1         = (const float*)d_in[13];
    const float* b1         = (const float*)d_in[14];
    const float* W2         = (const float*)d_in[15];
    const float* b2         = (const float*)d_in[16];
    const float* Wop        = (const float*)d_in[17];
    const float* bop        = (const float*)d_in[18];
    const float* relpos     = (const float*)d_in[19];
    const float* pair_ln_w  = (const float*)d_in[20];
    const float* pair_ln_b  = (const float*)d_in[21];
    const float* Wf1        = (const float*)d_in[22];
    const float* bf1        = (const float*)d_in[23];
    const float* Wf2        = (const float*)d_in[24];
    const float* bf2        = (const float*)d_in[25];

    float *x, *tmp, *h, *qkv, *ao, *ffn, *sbuf, *proj, *pm, *u, *tb;
    cudaGetSymbolAddress((void**)&x,   g_x);
    cudaGetSymbolAddress((void**)&tmp, g_tmp);
    cudaGetSymbolAddress((void**)&h,   g_h);
    cudaGetSymbolAddress((void**)&qkv, g_qkv);
    cudaGetSymbolAddress((void**)&ao,  g_ao);
    cudaGetSymbolAddress((void**)&ffn, g_ffn);
    cudaGetSymbolAddress((void**)&sbuf,g_s);
    cudaGetSymbolAddress((void**)&proj,g_proj);
    cudaGetSymbolAddress((void**)&pm,  g_pm);
    cudaGetSymbolAddress((void**)&u,   g_u);
    cudaGetSymbolAddress((void**)&tb,  g_t);

    float* q = qkv;
    float* k = qkv + (size_t)ROWS_ * D_;
    float* v = qkv + (size_t)2 * ROWS_ * D_;

    float* fout = (float*)d_out;                 // frames: ROWS_*16
    float* xout = fout + ROWS_ * 16;             // x: ROWS_*D_

    zero_kernel<<<(ROWS_ * 3 + 255) / 256, 256>>>(tb, ROWS_ * 3);
    embed_kernel<<<ROWS_, 256>>>(tokens, tok_emb, emb_ln_w, emb_ln_b, x);

    for (int l = 0; l < L_; l++) {
        const float* Wql = Wq + (size_t)l * D_ * D_;
        const float* Wkl = Wk + (size_t)l * D_ * D_;
        const float* Wvl = Wv + (size_t)l * D_ * D_;
        const float* Wol = Wo + (size_t)l * D_ * D_;
        const float* bol = bo + (size_t)l * D_;
        const float* W1l = W1 + (size_t)l * D_ * FF_;
        const float* b1l = b1 + (size_t)l * FF_;
        const float* W2l = W2 + (size_t)l * FF_ * D_;
        const float* b2l = b2 + (size_t)l * D_;

        // fused QKV: 144 blocks
        gemm_k<ROWS_, D_, D_, 64, 64, 0, false, 1>
            <<<dim3(4, 12, 3), 256>>>(x, Wql, Wkl, Wvl, nullptr, nullptr, qkv, nullptr);

        // scores: S[z] = QK^T/sqrt(dh) - d2, 576 blocks
        gemm_k<384, 384, 32, 64, 64, 0, false, 2>
            <<<dim3(6, 6, 16), 256>>>(q, k, nullptr, nullptr, nullptr, nullptr, sbuf, tb);

        // softmax over j per (z,i) row
        softmax_kernel<<<768, 256>>>(sbuf);

        // AV: ao(b,:,h) = P[z] @ V(b,:,h), 96 blocks
        gemm_k<384, 32, 384, 64, 32, 0, false, 3>
            <<<dim3(1, 6, 16), 256>>>(sbuf, v, nullptr, nullptr, nullptr, nullptr, ao, nullptr);

        // tmp = x + ao@Wo + bo
        gemm_k<ROWS_, D_, D_, 32, 64, 0, true, 0>
            <<<dim3(4, 24), 256>>>(ao, Wol, nullptr, nullptr, bol, x, tmp, nullptr);
        // x = LN1(tmp); h = LN2(x)   (fused dual layernorm)
        ln2_kernel<<<ROWS_, 256>>>(tmp, attn_ln_w + l * D_, attn_ln_b + l * D_,
                                   ff_ln_w + l * D_, ff_ln_b + l * D_, x, h);

        // FFN
        gemm_k<ROWS_, FF_, D_, 64, 64, 2, false, 0>
            <<<dim3(16, 12), 256>>>(h, W1l, nullptr, nullptr, b1l, nullptr, ffn, nullptr);
        gemm_k<ROWS_, D_, FF_, 32, 64, 0, true, 0>
            <<<dim3(4, 24), 256>>>(ffn, W2l, nullptr, nullptr, b2l, x, x, nullptr);

        // proj = relu(x@Wop + bop)
        gemm_k<ROWS_, PD_, D_, 32, 64, 1, false, 0>
            <<<dim3(1, 24), 256>>>(x, Wop, nullptr, nullptr, bop, nullptr, proj, nullptr);

        // pair LN + mean (fused)
        pair_kernel<<<ROWS_, 512>>>(proj, relpos, pair_ln_w, pair_ln_b, pm);

        // u = silu([x|pm]@Wf1 + bf1)   (concat fused into A-load)
        gemm_k<ROWS_, 128, FEAT_, 32, 64, 3, false, 4>
            <<<dim3(2, 24), 256>>>(x, Wf1, pm, nullptr, bf1, nullptr, u, nullptr);

        // frames (into d_out) + t buffer
        frame_kernel<<<ROWS_, 128>>>(u, Wf2, bf2, fout, tb);
    }

    copy_kernel<<<ROWS_, 256>>>(x, xout);
}

// round 6
// speedup vs baseline: 1.0328x; 1.0317x over previous
#include <cuda_runtime.h>
#include <math.h>

// ---------------- problem constants ----------------
#define B_ 2
#define N_ 384
#define D_ 256
#define H_ 8
#define DH_ 32
#define PD_ 64
#define L_ 8
#define ROWS_ (B_*N_)      // 768
#define FF_ 1024
#define FEAT_ 320          // D + PD

// ---------------- scratch buffers ----------------
__device__ __align__(16) float g_x   [ROWS_*D_];
__device__ __align__(16) float g_tmp [ROWS_*D_];
__device__ __align__(16) float g_h   [ROWS_*D_];
__device__ __align__(16) float g_qkv [3*ROWS_*D_];
__device__ __align__(16) float g_ao  [ROWS_*D_];
__device__ __align__(16) float g_ffn [ROWS_*FF_];
__device__ __align__(16) float g_s   [16*384*384];   // scores [b*8+h][i][j]
__device__ __align__(16) float g_proj[ROWS_*PD_];
__device__ __align__(16) float g_pm  [ROWS_*PD_];
__device__ __align__(16) float g_u   [ROWS_*128];
__device__ __align__(16) float g_t   [ROWS_*3];

// ---------------- reductions ----------------
__device__ __forceinline__ float2 block_sum2_256(float a, float b) {
    __shared__ float sa[8], sb[8];
    int lane = threadIdx.x & 31, wid = threadIdx.x >> 5;
#pragma unroll
    for (int o = 16; o > 0; o >>= 1) {
        a += __shfl_xor_sync(0xffffffffu, a, o);
        b += __shfl_xor_sync(0xffffffffu, b, o);
    }
    if (lane == 0) { sa[wid] = a; sb[wid] = b; }
    __syncthreads();
    if (threadIdx.x == 0) {
        float A = sa[0], Bv = sb[0];
        for (int w = 1; w < 8; w++) { A += sa[w]; Bv += sb[w]; }
        sa[0] = A; sb[0] = Bv;
    }
    __syncthreads();
    float2 r = make_float2(sa[0], sb[0]);
    __syncthreads();
    return r;
}

// ---------------- embedding + pos-enc + layernorm ----------------
__global__ void embed_kernel(const int* __restrict__ tokens,
                             const float* __restrict__ tok_emb,
                             const float* __restrict__ w,
                             const float* __restrict__ b,
                             float* __restrict__ out) {
    int row = blockIdx.x;
    int n = row % N_;
    int c = threadIdx.x;
    int tok = tokens[row];
    float val = tok_emb[tok * D_ + c];
    int half = c >> 1;
    float div = expf((float)(2 * half) * (-9.210340371976184f / (float)D_));
    float ang = (float)n * div;
    val += (c & 1) ? cosf(ang) : sinf(ang);
    float2 s = block_sum2_256(val, val * val);
    float m = s.x * (1.f / D_);
    float var = s.y * (1.f / D_) - m * m;
    out[row * D_ + c] = (val - m) * rsqrtf(var + 1e-5f) * w[c] + b[c];
}

// ---------------- dual layernorm: x = LN1(tmp); h = LN2(x) ----------------
__global__ void ln2_kernel(const float* __restrict__ in,
                           const float* __restrict__ w1, const float* __restrict__ b1,
                           const float* __restrict__ w2, const float* __restrict__ b2,
                           float* __restrict__ xo, float* __restrict__ ho) {
    int row = blockIdx.x;
    int c = threadIdx.x;
    float v = in[row * D_ + c];
    float2 s = block_sum2_256(v, v * v);
    float m = s.x * (1.f / D_);
    float var = s.y * (1.f / D_) - m * m;
    float x1 = (v - m) * rsqrtf(var + 1e-5f) * w1[c] + b1[c];
    xo[row * D_ + c] = x1;
    float2 s2 = block_sum2_256(x1, x1 * x1);
    float m2 = s2.x * (1.f / D_);
    float var2 = s2.y * (1.f / D_) - m2 * m2;
    ho[row * D_ + c] = (x1 - m2) * rsqrtf(var2 + 1e-5f) * w2[c] + b2[c];
}

// ---------------- generic double-buffered GEMM ----------------
// MODE 0: plain C = act(A@B0 + bias (+res))
// MODE 1: QKV batched (z picks weight among B0/B1/B2, C offset z*M*N)
// MODE 2: scores, batched over z=(b*8+h): A=Q(b,:,h), B=K(b,:,h) transposed,
//         C[z] = (A@B^T)/sqrt(32) - d2(i,j)   (tb = translations)
// MODE 3: AV batched: A=P[z], B=V(b,:,h), C=ao(b,:,h)
// MODE 4: A is concat [x(256) | pm(64)]: A param = x, B1 param = pm
template<int M, int N, int K, int TM, int TN, int ACT, bool RES, int MODE>
__global__ __launch_bounds__(256) void gemm_k(
    const float* __restrict__ Abase, const float* __restrict__ Bb0,
    const float* __restrict__ Bb1,   const float* __restrict__ Bb2,
    const float* __restrict__ bias,  const float* __restrict__ res,
    float* __restrict__ Cbase,       const float* __restrict__ tb) {
    constexpr int TX = TN / 4;
    constexpr int TY = 256 / TX;
    constexpr int RM = TM / TY;
    constexpr int S  = K / 16;
    constexpr int A4TOT = TM * 4;                 // float4 loads for A slice
    constexpr int ALOOP = (A4TOT + 255) / 256;
    constexpr int B4TOT = TN * 4;
    constexpr int BLOOP = (B4TOT + 255) / 256;

    __shared__ alignas(16) float As[2][16][TM];
    __shared__ alignas(16) float Bs[2][16][TN];

    int t = threadIdx.x;
    int m0 = blockIdx.y * TM, n0 = blockIdx.x * TN;
    int z = blockIdx.z;

    const float* A; const float* Bp; float* C;
    int lda, ldb, ldc;
    int bidx = 0;
    if (MODE == 0 || MODE == 4) { A = Abase; Bp = Bb0; C = Cbase; lda = K; ldb = N; ldc = N; }
    else if (MODE == 1) {
        A = Abase; Bp = (z == 0) ? Bb0 : (z == 1) ? Bb1 : Bb2;
        C = Cbase + (size_t)z * M * N; lda = K; ldb = N; ldc = N;
    } else if (MODE == 2) {
        bidx = z >> 3; int h = z & 7;
        A  = Abase + (size_t)bidx * N_ * D_ + h * DH_;
        Bp = Bb0   + (size_t)bidx * N_ * D_ + h * DH_;
        C  = Cbase + (size_t)z * M * N;
        lda = D_; ldb = D_; ldc = N;
    } else {
        bidx = z >> 3; int h = z & 7;
        A  = Abase + (size_t)z * M * K;
        Bp = Bb0   + (size_t)bidx * N_ * D_ + h * DH_;
        C  = Cbase + (size_t)bidx * N_ * D_ + h * DH_;
        lda = K; ldb = D_; ldc = D_;
    }

    int tx = t % TX, ty = t / TX;

    float4 pa[ALOOP], pb[BLOOP];
    auto loadA = [&](int s) {
#pragma unroll
        for (int u = 0; u < ALOOP; u++) {
            int f = t + u * 256;
            if ((A4TOT % 256) && f >= A4TOT) break;
            int ar = f >> 2, ak = (f & 3) * 4;
            int col = s * 16 + ak;
            if (MODE == 4) {
                const float* src = (col < 256)
                    ? &Abase[(size_t)(m0 + ar) * 256 + col]
                    : &Bb1[(size_t)(m0 + ar) * 64 + (col - 256)];
                pa[u] = *(const float4*)src;
            } else {
                pa[u] = *(const float4*)&A[(size_t)(m0 + ar) * lda + col];
            }
        }
    };
    auto storeA = [&](int buf) {
#pragma unroll
        for (int u = 0; u < ALOOP; u++) {
            int f = t + u * 256;
            if ((A4TOT % 256) && f >= A4TOT) break;
            int ar = f >> 2, ak = (f & 3) * 4;
            As[buf][ak + 0][ar] = pa[u].x; As[buf][ak + 1][ar] = pa[u].y;
            As[buf][ak + 2][ar] = pa[u].z; As[buf][ak + 3][ar] = pa[u].w;
        }
    };
    auto loadB = [&](int s) {
#pragma unroll
        for (int u = 0; u < BLOOP; u++) {
            int f = t + u * 256;
            if ((B4TOT % 256) && f >= B4TOT) break;
            if (MODE == 2) {
                int br = f >> 2, bk = (f & 3) * 4;
                pb[u] = *(const float4*)&Bp[(size_t)(n0 + br) * ldb + s * 16 + bk];
            } else {
                int br = f / TX, bc = (f % TX) * 4;
                pb[u] = *(const float4*)&Bp[(size_t)(s * 16 + br) * ldb + n0 + bc];
            }
        }
    };
    auto storeB = [&](int buf) {
#pragma unroll
        for (int u = 0; u < BLOOP; u++) {
            int f = t + u * 256;
            if ((B4TOT % 256) && f >= B4TOT) break;
            if (MODE == 2) {
                int br = f >> 2, bk = (f & 3) * 4;
                Bs[buf][bk + 0][br] = pb[u].x; Bs[buf][bk + 1][br] = pb[u].y;
                Bs[buf][bk + 2][br] = pb[u].z; Bs[buf][bk + 3][br] = pb[u].w;
            } else {
                int br = f / TX, bc = (f % TX) * 4;
                *(float4*)&Bs[buf][br][bc] = pb[u];
            }
        }
    };

    loadA(0); loadB(0);
    storeA(0); storeB(0);
    __syncthreads();

    float acc[RM][4];
#pragma unroll
    for (int i = 0; i < RM; i++)
#pragma unroll
        for (int j = 0; j < 4; j++) acc[i][j] = 0.f;

#pragma unroll 2
    for (int s = 0; s < S; s++) {
        int buf = s & 1;
        if (s + 1 < S) { loadA(s + 1); loadB(s + 1); }
#pragma unroll
        for (int k = 0; k < 16; k++) {
            float rb[4];
#pragma unroll
            for (int j = 0; j < 4; j++) rb[j] = Bs[buf][k][tx * 4 + j];
            float ra[RM];
#pragma unroll
            for (int i = 0; i < RM; i++) ra[i] = As[buf][k][ty * RM + i];
#pragma unroll
            for (int i = 0; i < RM; i++)
#pragma unroll
                for (int j = 0; j < 4; j++) acc[i][j] = fmaf(ra[i], rb[j], acc[i][j]);
        }
        if (s + 1 < S) { storeA((s + 1) & 1); storeB((s + 1) & 1); }
        __syncthreads();
    }

    // epilogue
    float tix[RM], tiy[RM], tiz[RM], tjx[4], tjy[4], tjz[4];
    if (MODE == 2) {
        const float* tbb = tb + (size_t)bidx * N_ * 3;
#pragma unroll
        for (int i = 0; i < RM; i++) {
            int m = m0 + ty * RM + i;
            tix[i] = tbb[m * 3 + 0]; tiy[i] = tbb[m * 3 + 1]; tiz[i] = tbb[m * 3 + 2];
        }
#pragma unroll
        for (int j = 0; j < 4; j++) {
            int n = n0 + tx * 4 + j;
            tjx[j] = tbb[n * 3 + 0]; tjy[j] = tbb[n * 3 + 1]; tjz[j] = tbb[n * 3 + 2];
        }
    }
#pragma unroll
    for (int i = 0; i < RM; i++) {
        int m = m0 + ty * RM + i;
#pragma unroll
        for (int j = 0; j < 4; j++) {
            int n = n0 + tx * 4 + j;
            float v = acc[i][j];
            if (MODE == 2) {
                float dx = tix[i] - tjx[j], dy = tiy[i] - tjy[j], dz = tiz[i] - tjz[j];
                v = v * 0.17677669529663687f - (dx * dx + dy * dy + dz * dz);
            }
            if (bias) v += bias[n];
            if (RES) v += res[(size_t)m * ldc + n];
            if (ACT == 1) v = fmaxf(v, 0.f);
            else if (ACT == 2) v = 0.5f * v * (1.f + erff(v * 0.7071067811865475f));
            else if (ACT == 3) v = v / (1.f + __expf(-v));
            C[(size_t)m * ldc + n] = v;
        }
    }
}

// ---------------- warp-per-row softmax over rows of length 384 ----------------
__global__ void softmax_kernel(float* __restrict__ S) {
    int r = blockIdx.x * 8 + (threadIdx.x >> 5);
    int l = threadIdx.x & 31;
    float* row = S + (size_t)r * 384;
    float v[12];
    float mx = -1e30f;
#pragma unroll
    for (int q = 0; q < 12; q++) { v[q] = row[l + q * 32]; mx = fmaxf(mx, v[q]); }
#pragma unroll
    for (int o = 16; o > 0; o >>= 1) mx = fmaxf(mx, __shfl_xor_sync(0xffffffffu, mx, o));
    float s = 0.f;
#pragma unroll
    for (int q = 0; q < 12; q++) { v[q] = __expf(v[q] - mx); s += v[q]; }
#pragma unroll
    for (int o = 16; o > 0; o >>= 1) s += __shfl_xor_sync(0xffffffffu, s, o);
    float inv = 1.f / s;
#pragma unroll
    for (int q = 0; q < 12; q++) row[l + q * 32] = v[q] * inv;
}

// ---------------- fused pair LN + mean: warp-per-j, 512 threads ----------------
__global__ __launch_bounds__(512) void pair_kernel(
        const float* __restrict__ proj, const float* __restrict__ relpos,
        const float* __restrict__ pw, const float* __restrict__ pb,
        float* __restrict__ pm) {
    int row = blockIdx.x;
    int b = row / N_, i = row % N_;
    int t = threadIdx.x;
    int w = t >> 5, l = t & 31;

    __shared__ float pi[PD_];
    __shared__ float accs[16][PD_];

    if (t < PD_) pi[t] = proj[row * PD_ + t];
    __syncthreads();

    float w0 = pw[l], w1 = pw[l + 32], bb0 = pb[l], bb1 = pb[l + 32];
    float p0 = pi[l], p1 = pi[l + 32];
    float a0 = 0.f, a1 = 0.f;
    for (int j = w; j < N_; j += 16) {
        int rel = min(64, max(-64, j - i)) + 64;
        const float* pj = proj + (size_t)(b * N_ + j) * PD_;
        const float* re = relpos + (size_t)rel * PD_;
        float v0 = p0 + pj[l] + re[l];
        float v1 = p1 + pj[l + 32] + re[l + 32];
        float s = v0 + v1, s2 = v0 * v0 + v1 * v1;
#pragma unroll
        for (int o = 16; o > 0; o >>= 1) {
            s  += __shfl_xor_sync(0xffffffffu, s, o);
            s2 += __shfl_xor_sync(0xffffffffu, s2, o);
        }
        float m = s * (1.f / PD_);
        float var = s2 * (1.f / PD_) - m * m;
        float rs = rsqrtf(var + 1e-5f);
        a0 += (v0 - m) * rs * w0 + bb0;
        a1 += (v1 - m) * rs * w1 + bb1;
    }
    accs[w][l] = a0; accs[w][l + 32] = a1;
    __syncthreads();
    if (t < PD_) {
        float s = 0.f;
#pragma unroll
        for (int ww = 0; ww < 16; ww++) s += accs[ww][t];
        pm[row * PD_ + t] = s * (1.f / N_);
    }
}

// ---------------- raw = u@Wf2 + bf2; rot6d; frames + t ----------------
__global__ void frame_kernel(const float* __restrict__ u, const float* __restrict__ Wf2,
                             const float* __restrict__ bf2,
                             float* __restrict__ frames, float* __restrict__ tb) {
    int row = blockIdx.x;
    int t = threadIdx.x;
    __shared__ float us[128];
    __shared__ float raw[9];
    us[t] = u[row * 128 + t];
    __syncthreads();
    if (t < 9) {
        float s = bf2[t];
        for (int k = 0; k < 128; k++) s += us[k] * Wf2[k * 9 + t];
        raw[t] = s;
    }
    __syncthreads();
    if (t == 0) {
        float a1x = raw[0], a1y = raw[1], a1z = raw[2];
        float a2x = raw[3], a2y = raw[4], a2z = raw[5];
        float n1 = sqrtf(a1x * a1x + a1y * a1y + a1z * a1z + 1e-8f);
        float b1x = a1x / n1, b1y = a1y / n1, b1z = a1z / n1;
        float d = b1x * a2x + b1y * a2y + b1z * a2z;
        float px = a2x - d * b1x, py = a2y - d * b1y, pz = a2z - d * b1z;
        float n2 = sqrtf(px * px + py * py + pz * pz + 1e-8f);
        float b2x = px / n2, b2y = py / n2, b2z = pz / n2;
        float b3x = b1y * b2z - b1z * b2y;
        float b3y = b1z * b2x - b1x * b2z;
        float b3z = b1x * b2y - b1y * b2x;
        float tx = raw[6], ty = raw[7], tz = raw[8];
        float* F = frames + (size_t)row * 16;
        F[0] = b1x; F[1] = b1y; F[2]  = b1z; F[3]  = tx;
        F[4] = b2x; F[5] = b2y; F[6]  = b2z; F[7]  = ty;
        F[8] = b3x; F[9] = b3y; F[10] = b3z; F[11] = tz;
        F[12] = 0.f; F[13] = 0.f; F[14] = 0.f; F[15] = 1.f;
        tb[row * 3 + 0] = tx; tb[row * 3 + 1] = ty; tb[row * 3 + 2] = tz;
    }
}

// ---------------- utility ----------------
__global__ void zero_kernel(float* p, int n) {
    int i = blockIdx.x * blockDim.x + threadIdx.x;
    if (i < n) p[i] = 0.f;
}
__global__ void copy_kernel(const float* __restrict__ src, float* __restrict__ dst) {
    dst[blockIdx.x * blockDim.x + threadIdx.x] = src[blockIdx.x * blockDim.x + threadIdx.x];
}

// ---------------- host ----------------
extern "C" void kernel_launch(void* const* d_in, const int* in_sizes, int n_in,
                              void* d_out, int out_size) {
    (void)in_sizes; (void)n_in; (void)out_size;
    const int*   tokens     = (const int*)d_in[0];
    const float* tok_emb    = (const float*)d_in[1];
    const float* emb_ln_w   = (const float*)d_in[2];
    const float* emb_ln_b   = (const float*)d_in[3];
    const float* Wq         = (const float*)d_in[4];
    const float* Wk         = (const float*)d_in[5];
    const float* Wv         = (const float*)d_in[6];
    const float* Wo         = (const float*)d_in[7];
    const float* bo         = (const float*)d_in[8];
    const float* attn_ln_w  = (const float*)d_in[9];
    const float* attn_ln_b  = (const float*)d_in[10];
    const float* ff_ln_w    = (const float*)d_in[11];
    const float* ff_ln_b    = (const float*)d_in[12];
    const float* W1         = (const float*)d_in[13];
    const float* b1         = (const float*)d_in[14];
    const float* W2         = (const float*)d_in[15];
    const float* b2         = (const float*)d_in[16];
    const float* Wop        = (const float*)d_in[17];
    const float* bop        = (const float*)d_in[18];
    const float* relpos     = (const float*)d_in[19];
    const float* pair_ln_w  = (const float*)d_in[20];
    const float* pair_ln_b  = (const float*)d_in[21];
    const float* Wf1        = (const float*)d_in[22];
    const float* bf1        = (const float*)d_in[23];
    const float* Wf2        = (const float*)d_in[24];
    const float* bf2        = (const float*)d_in[25];

    float *x, *tmp, *h, *qkv, *ao, *ffn, *sbuf, *proj, *pm, *u, *tb;
    cudaGetSymbolAddress((void**)&x,   g_x);
    cudaGetSymbolAddress((void**)&tmp, g_tmp);
    cudaGetSymbolAddress((void**)&h,   g_h);
    cudaGetSymbolAddress((void**)&qkv, g_qkv);
    cudaGetSymbolAddress((void**)&ao,  g_ao);
    cudaGetSymbolAddress((void**)&ffn, g_ffn);
    cudaGetSymbolAddress((void**)&sbuf,g_s);
    cudaGetSymbolAddress((void**)&proj,g_proj);
    cudaGetSymbolAddress((void**)&pm,  g_pm);
    cudaGetSymbolAddress((void**)&u,   g_u);
    cudaGetSymbolAddress((void**)&tb,  g_t);

    float* q = qkv;
    float* k = qkv + (size_t)ROWS_ * D_;
    float* v = qkv + (size_t)2 * ROWS_ * D_;

    float* fout = (float*)d_out;                 // frames: ROWS_*16
    float* xout = fout + ROWS_ * 16;             // x: ROWS_*D_

    // one side stream + small event pool, created once (host-side only; no device mem)
    static cudaStream_t sside = nullptr;
    static cudaEvent_t  evp[32];
    if (sside == nullptr) {
        cudaStreamCreateWithFlags(&sside, cudaStreamNonBlocking);
        for (int i = 0; i < 32; i++)
            cudaEventCreateWithFlags(&evp[i], cudaEventDisableTiming);
    }
    int evi = 0;

    zero_kernel<<<(ROWS_ * 3 + 255) / 256, 256>>>(tb, ROWS_ * 3);
    embed_kernel<<<ROWS_, 256>>>(tokens, tok_emb, emb_ln_w, emb_ln_b, x);

    // QKV for layer 0
    gemm_k<ROWS_, D_, D_, 128, 64, 0, false, 1>
        <<<dim3(4, 6, 3), 256>>>(x, Wq, Wk, Wv, nullptr, nullptr, qkv, nullptr);

    for (int l = 0; l < L_; l++) {
        const float* Wol = Wo + (size_t)l * D_ * D_;
        const float* bol = bo + (size_t)l * D_;
        const float* W1l = W1 + (size_t)l * D_ * FF_;
        const float* b1l = b1 + (size_t)l * FF_;
        const float* W2l = W2 + (size_t)l * FF_ * D_;
        const float* b2l = b2 + (size_t)l * D_;

        // scores: S[z] = QK^T/sqrt(dh) - d2, 576 blocks
        gemm_k<384, 384, 32, 64, 64, 0, false, 2>
            <<<dim3(6, 6, 16), 256>>>(q, k, nullptr, nullptr, nullptr, nullptr, sbuf, tb);

        // softmax over j per (z,i) row
        softmax_kernel<<<768, 256>>>(sbuf);

        // AV: ao(b,:,h) = P[z] @ V(b,:,h), 96 blocks
        gemm_k<384, 32, 384, 64, 32, 0, false, 3>
            <<<dim3(1, 6, 16), 256>>>(sbuf, v, nullptr, nullptr, nullptr, nullptr, ao, nullptr);

        // tmp = x + ao@Wo + bo
        gemm_k<ROWS_, D_, D_, 32, 64, 0, true, 0>
            <<<dim3(4, 24), 256>>>(ao, Wol, nullptr, nullptr, bol, x, tmp, nullptr);
        // x = LN1(tmp); h = LN2(x)
        ln2_kernel<<<ROWS_, 256>>>(tmp, attn_ln_w + l * D_, attn_ln_b + l * D_,
                                   ff_ln_w + l * D_, ff_ln_b + l * D_, x, h);

        // FFN
        gemm_k<ROWS_, FF_, D_, 128, 64, 2, false, 0>
            <<<dim3(16, 6), 256>>>(h, W1l, nullptr, nullptr, b1l, nullptr, ffn, nullptr);
        gemm_k<ROWS_, D_, FF_, 32, 64, 0, true, 0>
            <<<dim3(4, 24), 256>>>(ffn, W2l, nullptr, nullptr, b2l, x, x, nullptr);
        // ---- x(l) final here ----

        // fork: frame chain on side stream, concurrent with next-layer QKV
        cudaEvent_t eFork = evp[evi++];
        cudaEventRecord(eFork, 0);
        cudaStreamWaitEvent(sside, eFork, 0);

        gemm_k<ROWS_, PD_, D_, 32, 64, 1, false, 0>
            <<<dim3(1, 24), 256, 0, sside>>>(x, Wop, nullptr, nullptr, bop, nullptr, proj, nullptr);
        pair_kernel<<<ROWS_, 512, 0, sside>>>(proj, relpos, pair_ln_w, pair_ln_b, pm);
        gemm_k<ROWS_, 128, FEAT_, 32, 64, 3, false, 4>
            <<<dim3(2, 24), 256, 0, sside>>>(x, Wf1, pm, nullptr, bf1, nullptr, u, nullptr);
        frame_kernel<<<ROWS_, 128, 0, sside>>>(u, Wf2, bf2, fout, tb);

        cudaEvent_t eJoin = evp[evi++];
        cudaEventRecord(eJoin, sside);

        // main stream: next layer's QKV (depends only on x)
        if (l + 1 < L_) {
            gemm_k<ROWS_, D_, D_, 128, 64, 0, false, 1>
                <<<dim3(4, 6, 3), 256>>>(x,
                    Wq + (size_t)(l + 1) * D_ * D_,
                    Wk + (size_t)(l + 1) * D_ * D_,
                    Wv + (size_t)(l + 1) * D_ * D_, nullptr, nullptr, qkv, nullptr);
        }

        // join: scores(l+1) needs tb from frame(l)
        cudaStreamWaitEvent(0, eJoin, 0);
    }

    copy_kernel<<<ROWS_, 256>>>(x, xout);
}

// round 7
// speedup vs baseline: 1.0461x; 1.0128x over previous
#include <cuda_runtime.h>
#include <math.h>

// ---------------- problem constants ----------------
#define B_ 2
#define N_ 384
#define D_ 256
#define H_ 8
#define DH_ 32
#define PD_ 64
#define L_ 8
#define ROWS_ (B_*N_)      // 768
#define FF_ 1024
#define FEAT_ 320          // D + PD

// ---------------- scratch buffers ----------------
__device__ __align__(16) float g_x   [ROWS_*D_];
__device__ __align__(16) float g_tmp [ROWS_*D_];
__device__ __align__(16) float g_h   [ROWS_*D_];
__device__ __align__(16) float g_qkv [3*ROWS_*D_];
__device__ __align__(16) float g_ao  [ROWS_*D_];
__device__ __align__(16) float g_ffn [ROWS_*FF_];
__device__ __align__(16) float g_s   [16*384*384];   // scores [b*8+h][i][j]
__device__ __align__(16) float g_proj[ROWS_*PD_];
__device__ __align__(16) float g_pm  [ROWS_*PD_];
__device__ __align__(16) float g_u   [ROWS_*128];
__device__ __align__(16) float g_t   [ROWS_*3];

// ---------------- reductions ----------------
__device__ __forceinline__ float2 block_sum2_256(float a, float b) {
    __shared__ float sa[8], sb[8];
    int lane = threadIdx.x & 31, wid = threadIdx.x >> 5;
#pragma unroll
    for (int o = 16; o > 0; o >>= 1) {
        a += __shfl_xor_sync(0xffffffffu, a, o);
        b += __shfl_xor_sync(0xffffffffu, b, o);
    }
    if (lane == 0) { sa[wid] = a; sb[wid] = b; }
    __syncthreads();
    if (threadIdx.x == 0) {
        float A = sa[0], Bv = sb[0];
        for (int w = 1; w < 8; w++) { A += sa[w]; Bv += sb[w]; }
        sa[0] = A; sb[0] = Bv;
    }
    __syncthreads();
    float2 r = make_float2(sa[0], sb[0]);
    __syncthreads();
    return r;
}

// ---------------- embedding + pos-enc + layernorm ----------------
__global__ void embed_kernel(const int* __restrict__ tokens,
                             const float* __restrict__ tok_emb,
                             const float* __restrict__ w,
                             const float* __restrict__ b,
                             float* __restrict__ out) {
    int row = blockIdx.x;
    int n = row % N_;
    int c = threadIdx.x;
    int tok = tokens[row];
    float val = tok_emb[tok * D_ + c];
    int half = c >> 1;
    float div = expf((float)(2 * half) * (-9.210340371976184f / (float)D_));
    float ang = (float)n * div;
    val += (c & 1) ? cosf(ang) : sinf(ang);
    float2 s = block_sum2_256(val, val * val);
    float m = s.x * (1.f / D_);
    float var = s.y * (1.f / D_) - m * m;
    out[row * D_ + c] = (val - m) * rsqrtf(var + 1e-5f) * w[c] + b[c];
}

// ---------------- dual layernorm: x = LN1(tmp); h = LN2(x) ----------------
__global__ void ln2_kernel(const float* __restrict__ in,
                           const float* __restrict__ w1, const float* __restrict__ b1,
                           const float* __restrict__ w2, const float* __restrict__ b2,
                           float* __restrict__ xo, float* __restrict__ ho) {
    int row = blockIdx.x;
    int c = threadIdx.x;
    float v = in[row * D_ + c];
    float2 s = block_sum2_256(v, v * v);
    float m = s.x * (1.f / D_);
    float var = s.y * (1.f / D_) - m * m;
    float x1 = (v - m) * rsqrtf(var + 1e-5f) * w1[c] + b1[c];
    xo[row * D_ + c] = x1;
    float2 s2 = block_sum2_256(x1, x1 * x1);
    float m2 = s2.x * (1.f / D_);
    float var2 = s2.y * (1.f / D_) - m2 * m2;
    ho[row * D_ + c] = (x1 - m2) * rsqrtf(var2 + 1e-5f) * w2[c] + b2[c];
}

// ---------------- generic double-buffered GEMM ----------------
// MODE 0: plain C = act(A@B0 + bias (+res))
// MODE 1: QKV batched (z picks weight among B0/B1/B2, C offset z*M*N)
// MODE 2: raw scores, batched z=(b*8+h): A=Q(b,:,h), B=K(b,:,h) transposed,
//         C[z] = (A@B^T)/sqrt(32)     (NO d2 bias here — fused into softmax)
// MODE 3: AV batched: A=P[z], B=V(b,:,h), C=ao(b,:,h)
// MODE 4: A is concat [x(256) | pm(64)]: A param = x, B1 param = pm
template<int M, int N, int K, int TM, int TN, int ACT, bool RES, int MODE>
__global__ __launch_bounds__(256) void gemm_k(
    const float* __restrict__ Abase, const float* __restrict__ Bb0,
    const float* __restrict__ Bb1,   const float* __restrict__ Bb2,
    const float* __restrict__ bias,  const float* __restrict__ res,
    float* __restrict__ Cbase) {
    constexpr int TX = TN / 4;
    constexpr int TY = 256 / TX;
    constexpr int RM = TM / TY;
    constexpr int S  = K / 16;
    constexpr int A4TOT = TM * 4;
    constexpr int ALOOP = (A4TOT + 255) / 256;
    constexpr int B4TOT = TN * 4;
    constexpr int BLOOP = (B4TOT + 255) / 256;

    __shared__ alignas(16) float As[2][16][TM];
    __shared__ alignas(16) float Bs[2][16][TN];

    int t = threadIdx.x;
    int m0 = blockIdx.y * TM, n0 = blockIdx.x * TN;
    int z = blockIdx.z;

    const float* A; const float* Bp; float* C;
    int lda, ldb, ldc;
    if (MODE == 0 || MODE == 4) { A = Abase; Bp = Bb0; C = Cbase; lda = K; ldb = N; ldc = N; }
    else if (MODE == 1) {
        A = Abase; Bp = (z == 0) ? Bb0 : (z == 1) ? Bb1 : Bb2;
        C = Cbase + (size_t)z * M * N; lda = K; ldb = N; ldc = N;
    } else if (MODE == 2) {
        int bidx = z >> 3; int h = z & 7;
        A  = Abase + (size_t)bidx * N_ * D_ + h * DH_;
        Bp = Bb0   + (size_t)bidx * N_ * D_ + h * DH_;
        C  = Cbase + (size_t)z * M * N;
        lda = D_; ldb = D_; ldc = N;
    } else {
        int bidx = z >> 3; int h = z & 7;
        A  = Abase + (size_t)z * M * K;
        Bp = Bb0   + (size_t)bidx * N_ * D_ + h * DH_;
        C  = Cbase + (size_t)bidx * N_ * D_ + h * DH_;
        lda = K; ldb = D_; ldc = D_;
    }

    int tx = t % TX, ty = t / TX;

    float4 pa[ALOOP], pb[BLOOP];
    auto loadA = [&](int s) {
#pragma unroll
        for (int u = 0; u < ALOOP; u++) {
            int f = t + u * 256;
            if ((A4TOT % 256) && f >= A4TOT) break;
            int ar = f >> 2, ak = (f & 3) * 4;
            int col = s * 16 + ak;
            if (MODE == 4) {
                const float* src = (col < 256)
                    ? &Abase[(size_t)(m0 + ar) * 256 + col]
                    : &Bb1[(size_t)(m0 + ar) * 64 + (col - 256)];
                pa[u] = *(const float4*)src;
            } else {
                pa[u] = *(const float4*)&A[(size_t)(m0 + ar) * lda + col];
            }
        }
    };
    auto storeA = [&](int buf) {
#pragma unroll
        for (int u = 0; u < ALOOP; u++) {
            int f = t + u * 256;
            if ((A4TOT % 256) && f >= A4TOT) break;
            int ar = f >> 2, ak = (f & 3) * 4;
            As[buf][ak + 0][ar] = pa[u].x; As[buf][ak + 1][ar] = pa[u].y;
            As[buf][ak + 2][ar] = pa[u].z; As[buf][ak + 3][ar] = pa[u].w;
        }
    };
    auto loadB = [&](int s) {
#pragma unroll
        for (int u = 0; u < BLOOP; u++) {
            int f = t + u * 256;
            if ((B4TOT % 256) && f >= B4TOT) break;
            if (MODE == 2) {
                int br = f >> 2, bk = (f & 3) * 4;
                pb[u] = *(const float4*)&Bp[(size_t)(n0 + br) * ldb + s * 16 + bk];
            } else {
                int br = f / TX, bc = (f % TX) * 4;
                pb[u] = *(const float4*)&Bp[(size_t)(s * 16 + br) * ldb + n0 + bc];
            }
        }
    };
    auto storeB = [&](int buf) {
#pragma unroll
        for (int u = 0; u < BLOOP; u++) {
            int f = t + u * 256;
            if ((B4TOT % 256) && f >= B4TOT) break;
            if (MODE == 2) {
                int br = f >> 2, bk = (f & 3) * 4;
                Bs[buf][bk + 0][br] = pb[u].x; Bs[buf][bk + 1][br] = pb[u].y;
                Bs[buf][bk + 2][br] = pb[u].z; Bs[buf][bk + 3][br] = pb[u].w;
            } else {
                int br = f / TX, bc = (f % TX) * 4;
                *(float4*)&Bs[buf][br][bc] = pb[u];
            }
        }
    };

    loadA(0); loadB(0);
    storeA(0); storeB(0);
    __syncthreads();

    float acc[RM][4];
#pragma unroll
    for (int i = 0; i < RM; i++)
#pragma unroll
        for (int j = 0; j < 4; j++) acc[i][j] = 0.f;

#pragma unroll 2
    for (int s = 0; s < S; s++) {
        int buf = s & 1;
        if (s + 1 < S) { loadA(s + 1); loadB(s + 1); }
#pragma unroll
        for (int k = 0; k < 16; k++) {
            float rb[4];
#pragma unroll
            for (int j = 0; j < 4; j++) rb[j] = Bs[buf][k][tx * 4 + j];
            float ra[RM];
#pragma unroll
            for (int i = 0; i < RM; i++) ra[i] = As[buf][k][ty * RM + i];
#pragma unroll
            for (int i = 0; i < RM; i++)
#pragma unroll
                for (int j = 0; j < 4; j++) acc[i][j] = fmaf(ra[i], rb[j], acc[i][j]);
        }
        if (s + 1 < S) { storeA((s + 1) & 1); storeB((s + 1) & 1); }
        __syncthreads();
    }

#pragma unroll
    for (int i = 0; i < RM; i++) {
        int m = m0 + ty * RM + i;
#pragma unroll
        for (int j = 0; j < 4; j++) {
            int n = n0 + tx * 4 + j;
            float v = acc[i][j];
            if (MODE == 2) v *= 0.17677669529663687f;   // 1/sqrt(32)
            if (bias) v += bias[n];
            if (RES) v += res[(size_t)m * ldc + n];
            if (ACT == 1) v = fmaxf(v, 0.f);
            else if (ACT == 2) v = 0.5f * v * (1.f + erff(v * 0.7071067811865475f));
            else if (ACT == 3) v = v / (1.f + __expf(-v));
            C[(size_t)m * ldc + n] = v;
        }
    }
}

// ---------------- softmax with fused -d2 bias: warp per (z,i) row ----------------
__global__ void softmax_bias_kernel(float* __restrict__ S, const float* __restrict__ tb) {
    int r = blockIdx.x * 8 + (threadIdx.x >> 5);   // r = z*384 + i
    int l = threadIdx.x & 31;
    int z = r / 384, i = r - z * 384;
    int b = z >> 3;
    const float* tbb = tb + (size_t)b * N_ * 3;
    float tix = tbb[i * 3], tiy = tbb[i * 3 + 1], tiz = tbb[i * 3 + 2];
    float* row = S + (size_t)r * 384;
    float v[12];
    float mx = -1e30f;
#pragma unroll
    for (int q = 0; q < 12; q++) {
        int j = l + q * 32;
        float dx = tix - tbb[j * 3], dy = tiy - tbb[j * 3 + 1], dz = tiz - tbb[j * 3 + 2];
        v[q] = row[j] - (dx * dx + dy * dy + dz * dz);
        mx = fmaxf(mx, v[q]);
    }
#pragma unroll
    for (int o = 16; o > 0; o >>= 1) mx = fmaxf(mx, __shfl_xor_sync(0xffffffffu, mx, o));
    float s = 0.f;
#pragma unroll
    for (int q = 0; q < 12; q++) { v[q] = __expf(v[q] - mx); s += v[q]; }
#pragma unroll
    for (int o = 16; o > 0; o >>= 1) s += __shfl_xor_sync(0xffffffffu, s, o);
    float inv = 1.f / s;
#pragma unroll
    for (int q = 0; q < 12; q++) row[l + q * 32] = v[q] * inv;
}

// ---------------- fused pair LN + mean: warp-per-j, 512 threads ----------------
__global__ __launch_bounds__(512) void pair_kernel(
        const float* __restrict__ proj, const float* __restrict__ relpos,
        const float* __restrict__ pw, const float* __restrict__ pb,
        float* __restrict__ pm) {
    int row = blockIdx.x;
    int b = row / N_, i = row % N_;
    int t = threadIdx.x;
    int w = t >> 5, l = t & 31;

    __shared__ float pi[PD_];
    __shared__ float accs[16][PD_];

    if (t < PD_) pi[t] = proj[row * PD_ + t];
    __syncthreads();

    float w0 = pw[l], w1 = pw[l + 32], bb0 = pb[l], bb1 = pb[l + 32];
    float p0 = pi[l], p1 = pi[l + 32];
    float a0 = 0.f, a1 = 0.f;
    for (int j = w; j < N_; j += 16) {
        int rel = min(64, max(-64, j - i)) + 64;
        const float* pj = proj + (size_t)(b * N_ + j) * PD_;
        const float* re = relpos + (size_t)rel * PD_;
        float v0 = p0 + pj[l] + re[l];
        float v1 = p1 + pj[l + 32] + re[l + 32];
        float s = v0 + v1, s2 = v0 * v0 + v1 * v1;
#pragma unroll
        for (int o = 16; o > 0; o >>= 1) {
            s  += __shfl_xor_sync(0xffffffffu, s, o);
            s2 += __shfl_xor_sync(0xffffffffu, s2, o);
        }
        float m = s * (1.f / PD_);
        float var = s2 * (1.f / PD_) - m * m;
        float rs = rsqrtf(var + 1e-5f);
        a0 += (v0 - m) * rs * w0 + bb0;
        a1 += (v1 - m) * rs * w1 + bb1;
    }
    accs[w][l] = a0; accs[w][l + 32] = a1;
    __syncthreads();
    if (t < PD_) {
        float s = 0.f;
#pragma unroll
        for (int ww = 0; ww < 16; ww++) s += accs[ww][t];
        pm[row * PD_ + t] = s * (1.f / N_);
    }
}

// ---------------- raw = u@Wf2 + bf2; rot6d; frames + t ----------------
__global__ void frame_kernel(const float* __restrict__ u, const float* __restrict__ Wf2,
                             const float* __restrict__ bf2,
                             float* __restrict__ frames, float* __restrict__ tb) {
    int row = blockIdx.x;
    int t = threadIdx.x;
    __shared__ float us[128];
    __shared__ float raw[9];
    us[t] = u[row * 128 + t];
    __syncthreads();
    if (t < 9) {
        float s = bf2[t];
        for (int k = 0; k < 128; k++) s += us[k] * Wf2[k * 9 + t];
        raw[t] = s;
    }
    __syncthreads();
    if (t == 0) {
        float a1x = raw[0], a1y = raw[1], a1z = raw[2];
        float a2x = raw[3], a2y = raw[4], a2z = raw[5];
        float n1 = sqrtf(a1x * a1x + a1y * a1y + a1z * a1z + 1e-8f);
        float b1x = a1x / n1, b1y = a1y / n1, b1z = a1z / n1;
        float d = b1x * a2x + b1y * a2y + b1z * a2z;
        float px = a2x - d * b1x, py = a2y - d * b1y, pz = a2z - d * b1z;
        float n2 = sqrtf(px * px + py * py + pz * pz + 1e-8f);
        float b2x = px / n2, b2y = py / n2, b2z = pz / n2;
        float b3x = b1y * b2z - b1z * b2y;
        float b3y = b1z * b2x - b1x * b2z;
        float b3z = b1x * b2y - b1y * b2x;
        float tx = raw[6], ty = raw[7], tz = raw[8];
        float* F = frames + (size_t)row * 16;
        F[0] = b1x; F[1] = b1y; F[2]  = b1z; F[3]  = tx;
        F[4] = b2x; F[5] = b2y; F[6]  = b2z; F[7]  = ty;
        F[8] = b3x; F[9] = b3y; F[10] = b3z; F[11] = tz;
        F[12] = 0.f; F[13] = 0.f; F[14] = 0.f; F[15] = 1.f;
        tb[row * 3 + 0] = tx; tb[row * 3 + 1] = ty; tb[row * 3 + 2] = tz;
    }
}

// ---------------- utility ----------------
__global__ void zero_kernel(float* p, int n) {
    int i = blockIdx.x * blockDim.x + threadIdx.x;
    if (i < n) p[i] = 0.f;
}
__global__ void copy_kernel(const float* __restrict__ src, float* __restrict__ dst) {
    dst[blockIdx.x * blockDim.x + threadIdx.x] = src[blockIdx.x * blockDim.x + threadIdx.x];
}

// ---------------- host ----------------
extern "C" void kernel_launch(void* const* d_in, const int* in_sizes, int n_in,
                              void* d_out, int out_size) {
    (void)in_sizes; (void)n_in; (void)out_size;
    const int*   tokens     = (const int*)d_in[0];
    const float* tok_emb    = (const float*)d_in[1];
    const float* emb_ln_w   = (const float*)d_in[2];
    const float* emb_ln_b   = (const float*)d_in[3];
    const float* Wq         = (const float*)d_in[4];
    const float* Wk         = (const float*)d_in[5];
    const float* Wv         = (const float*)d_in[6];
    const float* Wo         = (const float*)d_in[7];
    const float* bo         = (const float*)d_in[8];
    const float* attn_ln_w  = (const float*)d_in[9];
    const float* attn_ln_b  = (const float*)d_in[10];
    const float* ff_ln_w    = (const float*)d_in[11];
    const float* ff_ln_b    = (const float*)d_in[12];
    const float* W1         = (const float*)d_in[13];
    const float* b1         = (const float*)d_in[14];
    const float* W2         = (const float*)d_in[15];
    const float* b2         = (const float*)d_in[16];
    const float* Wop        = (const float*)d_in[17];
    const float* bop        = (const float*)d_in[18];
    const float* relpos     = (const float*)d_in[19];
    const float* pair_ln_w  = (const float*)d_in[20];
    const float* pair_ln_b  = (const float*)d_in[21];
    const float* Wf1        = (const float*)d_in[22];
    const float* bf1        = (const float*)d_in[23];
    const float* Wf2        = (const float*)d_in[24];
    const float* bf2        = (const float*)d_in[25];

    float *x, *tmp, *h, *qkv, *ao, *ffn, *sbuf, *proj, *pm, *u, *tb;
    cudaGetSymbolAddress((void**)&x,   g_x);
    cudaGetSymbolAddress((void**)&tmp, g_tmp);
    cudaGetSymbolAddress((void**)&h,   g_h);
    cudaGetSymbolAddress((void**)&qkv, g_qkv);
    cudaGetSymbolAddress((void**)&ao,  g_ao);
    cudaGetSymbolAddress((void**)&ffn, g_ffn);
    cudaGetSymbolAddress((void**)&sbuf,g_s);
    cudaGetSymbolAddress((void**)&proj,g_proj);
    cudaGetSymbolAddress((void**)&pm,  g_pm);
    cudaGetSymbolAddress((void**)&u,   g_u);
    cudaGetSymbolAddress((void**)&tb,  g_t);

    float* q = qkv;
    float* k = qkv + (size_t)ROWS_ * D_;
    float* v = qkv + (size_t)2 * ROWS_ * D_;

    float* fout = (float*)d_out;                 // frames: ROWS_*16
    float* xout = fout + ROWS_ * 16;             // x: ROWS_*D_

    static cudaStream_t sside = nullptr;
    static cudaEvent_t  evp[40];
    if (sside == nullptr) {
        cudaStreamCreateWithFlags(&sside, cudaStreamNonBlocking);
        for (int i = 0; i < 40; i++)
            cudaEventCreateWithFlags(&evp[i], cudaEventDisableTiming);
    }
    int evi = 0;

    zero_kernel<<<(ROWS_ * 3 + 255) / 256, 256>>>(tb, ROWS_ * 3);
    embed_kernel<<<ROWS_, 256>>>(tokens, tok_emb, emb_ln_w, emb_ln_b, x);

    // layer-0 QKV + raw scores (no tb needed)
    gemm_k<ROWS_, D_, D_, 128, 64, 0, false, 1>
        <<<dim3(4, 6, 3), 256>>>(x, Wq, Wk, Wv, nullptr, nullptr, qkv);
    gemm_k<384, 384, 32, 128, 64, 0, false, 2>
        <<<dim3(6, 3, 16), 256>>>(q, k, nullptr, nullptr, nullptr, nullptr, sbuf);

    for (int l = 0; l < L_; l++) {
        const float* Wol = Wo + (size_t)l * D_ * D_;
        const float* bol = bo + (size_t)l * D_;
        const float* W1l = W1 + (size_t)l * D_ * FF_;
        const float* b1l = b1 + (size_t)l * FF_;
        const float* W2l = W2 + (size_t)l * FF_ * D_;
        const float* b2l = b2 + (size_t)l * D_;

        // softmax with fused -d2 bias (tb from frame(l-1) / zeros)
        softmax_bias_kernel<<<768, 256>>>(sbuf, tb);

        // AV: ao(b,:,h) = P[z] @ V(b,:,h)
        gemm_k<384, 32, 384, 64, 32, 0, false, 3>
            <<<dim3(1, 6, 16), 256>>>(sbuf, v, nullptr, nullptr, nullptr, nullptr, ao);

        // tmp = x + ao@Wo + bo
        gemm_k<ROWS_, D_, D_, 32, 64, 0, true, 0>
            <<<dim3(4, 24), 256>>>(ao, Wol, nullptr, nullptr, bol, x, tmp);
        // x = LN1(tmp); h = LN2(x)
        ln2_kernel<<<ROWS_, 256>>>(tmp, attn_ln_w + l * D_, attn_ln_b + l * D_,
                                   ff_ln_w + l * D_, ff_ln_b + l * D_, x, h);

        // FFN
        gemm_k<ROWS_, FF_, D_, 128, 64, 2, false, 0>
            <<<dim3(16, 6), 256>>>(h, W1l, nullptr, nullptr, b1l, nullptr, ffn);
        gemm_k<ROWS_, D_, FF_, 32, 64, 0, true, 0>
            <<<dim3(4, 24), 256>>>(ffn, W2l, nullptr, nullptr, b2l, x, x);
        // ---- x(l) final ----

        // fork: frame chain on side stream
        cudaEvent_t eFork = evp[evi++];
        cudaEventRecord(eFork, 0);
        cudaStreamWaitEvent(sside, eFork, 0);

        gemm_k<ROWS_, PD_, D_, 32, 64, 1, false, 0>
            <<<dim3(1, 24), 256, 0, sside>>>(x, Wop, nullptr, nullptr, bop, nullptr, proj);
        pair_kernel<<<ROWS_, 512, 0, sside>>>(proj, relpos, pair_ln_w, pair_ln_b, pm);
        gemm_k<ROWS_, 128, FEAT_, 32, 64, 3, false, 4>
            <<<dim3(2, 24), 256, 0, sside>>>(x, Wf1, pm, nullptr, bf1, nullptr, u);
        frame_kernel<<<ROWS_, 128, 0, sside>>>(u, Wf2, bf2, fout, tb);

        cudaEvent_t eJoin = evp[evi++];
        cudaEventRecord(eJoin, sside);

        // main stream overlap: next layer's QKV + raw scores (neither needs tb)
        if (l + 1 < L_) {
            gemm_k<ROWS_, D_, D_, 128, 64, 0, false, 1>
                <<<dim3(4, 6, 3), 256>>>(x,
                    Wq + (size_t)(l + 1) * D_ * D_,
                    Wk + (size_t)(l + 1) * D_ * D_,
                    Wv + (size_t)(l + 1) * D_ * D_, nullptr, nullptr, qkv);
            gemm_k<384, 384, 32, 128, 64, 0, false, 2>
                <<<dim3(6, 3, 16), 256>>>(q, k, nullptr, nullptr, nullptr, nullptr, sbuf);
        }

        // join: softmax(l+1) needs tb from frame(l)
        cudaStreamWaitEvent(0, eJoin, 0);
    }

    copy_kernel<<<ROWS_, 256>>>(x, xout);
}